// round 15
// baseline (speedup 1.0000x reference)
#include <cuda_runtime.h>
#include <math.h>

// Problem constants (fixed shapes from reference)
#define BB   2
#define NN   16384
#define MM   4096
#define CC   64
#define KK   16
#define NQ   (BB * MM)
#define TILE 2048
#define QPB  16            // queries per block
#define TPB  256           // threads per block (8 warps x 2 queries)

#define NBIN  1024
#define BINLO (-5.0f)
#define BINW  0.009765625f  /* 10/1024, exact in fp32 */
#define INVW  102.4f
#define STEPB 8             /* expansion step in bins */
#define PRIME 128           /* primed points per warp */

#define BIGF 1e30f
#define FULLMASK 0xffffffffu

// Scratch (__device__ globals; no allocs allowed)
__device__ float  g_xt[BB * NN * CC];      // transposed features (B,N,C)
__device__ float4 g_spts[BB * NN];         // x-sorted points (x,y,z,(float)orig_idx)
__device__ int    g_pstart[BB * (NBIN + 1)];
__device__ int    g_pcnt[BB * NBIN];
__device__ int    g_pcur[BB * NBIN];
__device__ int    g_qcnt[BB * NBIN];
__device__ int    g_qcur[BB * NBIN];
__device__ int    g_qorder[BB * MM];       // query ids sorted by x-bin

__device__ __forceinline__ int bin_of(float x) {
    return min(NBIN - 1, max(0, (int)floorf((x - BINLO) * INVW)));
}

// ---------------------------------------------------------------------------
// Build kernels
// ---------------------------------------------------------------------------
__global__ __launch_bounds__(256) void zero_kernel() {
    const int i = blockIdx.x * 256 + threadIdx.x;
    if (i < BB * NBIN) { g_pcnt[i] = 0; g_qcnt[i] = 0; }
}

__global__ __launch_bounds__(256) void count_kernel(const float* __restrict__ p1,
                                                    const float* __restrict__ p2) {
    if (blockIdx.x < 128) {
        const int i = blockIdx.x * 256 + threadIdx.x;          // 0..BB*NN-1
        atomicAdd(&g_pcnt[(i >> 14) * NBIN + bin_of(p1[3 * i])], 1);
    } else {
        const int i = (blockIdx.x - 128) * 256 + threadIdx.x;  // 0..BB*MM-1
        atomicAdd(&g_qcnt[(i >> 12) * NBIN + bin_of(p2[3 * i])], 1);
    }
}

__global__ __launch_bounds__(1024) void scan_kernel() {
    __shared__ int wsum[32];
    const int tid = threadIdx.x, lane = tid & 31, wid = tid >> 5;
    const int b = blockIdx.x & 1;
    const bool qrole = (blockIdx.x >= 2);
    const int v = qrole ? g_qcnt[b * NBIN + tid] : g_pcnt[b * NBIN + tid];
    int x = v;
#pragma unroll
    for (int o = 1; o < 32; o <<= 1) {
        const int t = __shfl_up_sync(FULLMASK, x, o);
        if (lane >= o) x += t;
    }
    if (lane == 31) wsum[wid] = x;
    __syncthreads();
    if (wid == 0) {
        const int wv = wsum[lane];
        int s = wv;
#pragma unroll
        for (int o = 1; o < 32; o <<= 1) {
            const int t = __shfl_up_sync(FULLMASK, s, o);
            if (lane >= o) s += t;
        }
        wsum[lane] = s - wv;
    }
    __syncthreads();
    const int excl = x - v + wsum[wid];
    if (qrole) {
        g_qcur[b * NBIN + tid] = excl;
    } else {
        g_pcur[b * NBIN + tid] = excl;
        g_pstart[b * (NBIN + 1) + tid] = excl;
        if (tid == 0) g_pstart[b * (NBIN + 1) + NBIN] = NN;
    }
}

__global__ __launch_bounds__(256) void scatter_kernel(const float* __restrict__ p1,
                                                      const float* __restrict__ p2) {
    if (blockIdx.x < 128) {
        const int i = blockIdx.x * 256 + threadIdx.x;
        const int b = i >> 14;
        const float x = p1[3 * i], y = p1[3 * i + 1], z = p1[3 * i + 2];
        const int pos = atomicAdd(&g_pcur[b * NBIN + bin_of(x)], 1);
        g_spts[b * NN + pos] = make_float4(x, y, z, (float)(i & (NN - 1)));
    } else {
        const int i = (blockIdx.x - 128) * 256 + threadIdx.x;
        const int b = i >> 12;
        const int pos = atomicAdd(&g_qcur[b * NBIN + bin_of(p2[3 * i])], 1);
        g_qorder[b * MM + pos] = i & (MM - 1);
    }
}

// ---------------------------------------------------------------------------
// Feature transpose x1 (B,C,N) -> g_xt (B,N,C)
// ---------------------------------------------------------------------------
__global__ __launch_bounds__(256) void transpose_kernel(const float* __restrict__ x1) {
    __shared__ float t[32][33];
    const int b  = blockIdx.z;
    const int n0 = blockIdx.x * 32;
    const int c0 = blockIdx.y * 32;
    const int tx = threadIdx.x;
    const int ty = threadIdx.y;

    const float* src = x1  + (size_t)b * CC * NN;
    float*       dst = g_xt + (size_t)b * NN * CC;

#pragma unroll
    for (int i = 0; i < 32; i += 8)
        t[ty + i][tx] = src[(size_t)(c0 + ty + i) * NN + (n0 + tx)];
    __syncthreads();
#pragma unroll
    for (int i = 0; i < 32; i += 8)
        dst[(size_t)(n0 + ty + i) * CC + (c0 + tx)] = t[tx][ty + i];
}

// ---------------------------------------------------------------------------
// KNN: block = 16 x-adjacent queries (8 warps x 2). Phase 1: each warp PRIMES
// its pair's top-16 from the 128 x-nearest sorted points (direct LDG) so the
// gate tau is near-final before any slab scanning. Phase 2: slab sized from
// primed tau, scanned block-cooperatively through smem tiles with the ballot
// hot loop; primed positions are skip-masked (no duplicates). Phase 3: exact
// block-uniform expansion loop (conservative fp margins -> over-scan only).
// Tie-stable (d', idx) selection => independent of scatter order.
// d' = |p|^2 - 2 q.p (order-equivalent); d16^2 = tau + |q|^2.
// ---------------------------------------------------------------------------
__global__ __launch_bounds__(TPB) void knn_kernel(const float* __restrict__ p2,
                                                  float* __restrict__ out) {
    __shared__ float4 sp[TILE];    // 32 KB
    __shared__ float  s_lo[8], s_hi[8];

    const int tid  = threadIdx.x;
    const int warp = tid >> 5, lane = tid & 31;
    const int b     = blockIdx.x >> 8;            // 256 blocks per batch
    const int qbase = (blockIdx.x & 255) * QPB;

    const int m0 = g_qorder[b * MM + qbase + 2 * warp];
    const int m1 = g_qorder[b * MM + qbase + 2 * warp + 1];

    const float* q0p = p2 + ((size_t)b * MM + m0) * 3;
    const float* q1p = p2 + ((size_t)b * MM + m1) * 3;
    const float qx0 = q0p[0], qy0 = q0p[1], qz0 = q0p[2];
    const float qx1 = q1p[0], qy1 = q1p[1], qz1 = q1p[2];
    const float n0x = -2.0f * qx0, n0y = -2.0f * qy0, n0z = -2.0f * qz0;
    const float n1x = -2.0f * qx1, n1y = -2.0f * qy1, n1z = -2.0f * qz1;
    const float qq0 = fmaf(qx0, qx0, fmaf(qy0, qy0, qz0 * qz0));
    const float qq1 = fmaf(qx1, qx1, fmaf(qy1, qy1, qz1 * qz1));

    const int bsb = b * (NBIN + 1);
    const float FINF = __int_as_float(0x7f800000);

    float topd = BIGF;           // sorted lists: q0 lanes 0..15, q1 lanes 16..31
    int   topi = 0x7fffffff;
    float tau0 = BIGF, tau1 = BIGF;

    auto ins0 = [&](float dc, int ic) {
        const unsigned mlt =
            __ballot_sync(FULLMASK, (topd < dc) || (topd == dc && topi < ic)) & 0xFFFFu;
        const int rank = __popc(mlt);
        const float pd = __shfl_up_sync(FULLMASK, topd, 1);
        const int   pi = __shfl_up_sync(FULLMASK, topi, 1);
        if (lane < 16) {
            if (lane == rank)     { topd = dc; topi = ic; }
            else if (lane > rank) { topd = pd; topi = pi; }
        }
    };
    auto ins1 = [&](float dc, int ic) {
        const int rank = 16 + __popc(
            __ballot_sync(FULLMASK, (topd < dc) || (topd == dc && topi < ic)) >> 16);
        const float pd = __shfl_up_sync(FULLMASK, topd, 1);
        const int   pi = __shfl_up_sync(FULLMASK, topi, 1);
        if (lane >= 16) {
            if (lane == rank)     { topd = dc; topi = ic; }
            else if (lane > rank) { topd = pd; topi = pi; }
        }
    };

    // ---- Phase 1: prime from the PRIME x-nearest sorted points (warp-local) ----
    const int qbA = bin_of(qx0), qbB = bin_of(qx1);
    const int pcA = (g_pstart[bsb + qbA] + g_pstart[bsb + qbA + 1]) >> 1;
    const int pcB = (g_pstart[bsb + qbB] + g_pstart[bsb + qbB + 1]) >> 1;
    int plo = ((pcA + pcB) >> 1) - PRIME / 2;
    plo = max(0, min(plo, NN - PRIME));
    const int phi = plo + PRIME;

    for (int t = plo; t < phi; t += 32) {
        const float4 P = g_spts[b * NN + t + lane];
        const float pp = fmaf(P.x, P.x, fmaf(P.y, P.y, P.z * P.z));
        const float d0 = fmaf(n0x, P.x, fmaf(n0y, P.y, fmaf(n0z, P.z, pp)));
        const float d1 = fmaf(n1x, P.x, fmaf(n1y, P.y, fmaf(n1z, P.z, pp)));
        const int idx = (int)P.w;
        unsigned ba = __ballot_sync(FULLMASK, d0 <= tau0);
        while (ba) {
            const int s2 = __ffs(ba) - 1; ba &= ba - 1;
            ins0(__shfl_sync(FULLMASK, d0, s2), __shfl_sync(FULLMASK, idx, s2));
        }
        tau0 = __shfl_sync(FULLMASK, topd, 15);
        unsigned bc = __ballot_sync(FULLMASK, d1 <= tau1);
        while (bc) {
            const int s2 = __ffs(bc) - 1; bc &= bc - 1;
            ins1(__shfl_sync(FULLMASK, d1, s2), __shfl_sync(FULLMASK, idx, s2));
        }
        tau1 = __shfl_sync(FULLMASK, topd, 31);
    }

    // ---- Slab bounds from primed tau (block-reduced) ----
    {
        const float t20 = tau0 + qq0, t21 = tau1 + qq1;
        const float w0 = sqrtf(fmaxf(t20, 0.0f)) + 0.02f;
        const float w1 = sqrtf(fmaxf(t21, 0.0f)) + 0.02f;
        const float wlo = fminf(qx0 - w0, qx1 - w1);
        const float whi = fmaxf(qx0 + w0, qx1 + w1);
        if (lane == 0) { s_lo[warp] = wlo; s_hi[warp] = whi; }
    }
    __syncthreads();
    float xlo = s_lo[0], xhi = s_hi[0];
#pragma unroll
    for (int i = 1; i < 8; i++) { xlo = fminf(xlo, s_lo[i]); xhi = fmaxf(xhi, s_hi[i]); }

#define KNN_CHUNK(J, CNT, GUARD, T0)                                             \
    {                                                                            \
        float d0a = FINF, d0b = FINF, d1a = FINF, d1b = FINF;                    \
        int ia = 0, ib = 0;                                                      \
        const int posA = (T0) + (J) + lane;                                      \
        const int posB = posA + 32;                                              \
        const bool okA = (!(GUARD) || (J) + lane < (CNT)) &&                     \
                         !((unsigned)(posA - plo) < (unsigned)PRIME);            \
        const bool okB = (!(GUARD) || (J) + 32 + lane < (CNT)) &&                \
                         !((unsigned)(posB - plo) < (unsigned)PRIME);            \
        if (okA) {                                                               \
            const float4 P = sp[(J) + lane];                                     \
            const float pp = fmaf(P.x, P.x, fmaf(P.y, P.y, P.z * P.z));          \
            d0a = fmaf(n0x, P.x, fmaf(n0y, P.y, fmaf(n0z, P.z, pp)));            \
            d1a = fmaf(n1x, P.x, fmaf(n1y, P.y, fmaf(n1z, P.z, pp)));            \
            ia = (int)P.w;                                                       \
        }                                                                        \
        if (okB) {                                                               \
            const float4 P = sp[(J) + 32 + lane];                                \
            const float pp = fmaf(P.x, P.x, fmaf(P.y, P.y, P.z * P.z));          \
            d0b = fmaf(n0x, P.x, fmaf(n0y, P.y, fmaf(n0z, P.z, pp)));            \
            d1b = fmaf(n1x, P.x, fmaf(n1y, P.y, fmaf(n1z, P.z, pp)));            \
            ib = (int)P.w;                                                       \
        }                                                                        \
        const unsigned g0 = __ballot_sync(FULLMASK, fminf(d0a, d0b) <= tau0);    \
        const unsigned g1 = __ballot_sync(FULLMASK, fminf(d1a, d1b) <= tau1);    \
        if (g0 | g1) {                                                           \
            if (g0) {                                                            \
                unsigned ba = __ballot_sync(FULLMASK, d0a <= tau0);              \
                while (ba) { const int s2 = __ffs(ba) - 1; ba &= ba - 1;         \
                    ins0(__shfl_sync(FULLMASK, d0a, s2),                         \
                         __shfl_sync(FULLMASK, ia, s2)); }                       \
                unsigned bc = __ballot_sync(FULLMASK, d0b <= tau0);              \
                while (bc) { const int s2 = __ffs(bc) - 1; bc &= bc - 1;         \
                    ins0(__shfl_sync(FULLMASK, d0b, s2),                         \
                         __shfl_sync(FULLMASK, ib, s2)); }                       \
                tau0 = __shfl_sync(FULLMASK, topd, 15);                          \
            }                                                                    \
            if (g1) {                                                            \
                unsigned ba = __ballot_sync(FULLMASK, d1a <= tau1);              \
                while (ba) { const int s2 = __ffs(ba) - 1; ba &= ba - 1;         \
                    ins1(__shfl_sync(FULLMASK, d1a, s2),                         \
                         __shfl_sync(FULLMASK, ia, s2)); }                       \
                unsigned bc = __ballot_sync(FULLMASK, d1b <= tau1);              \
                while (bc) { const int s2 = __ffs(bc) - 1; bc &= bc - 1;         \
                    ins1(__shfl_sync(FULLMASK, d1b, s2),                         \
                         __shfl_sync(FULLMASK, ib, s2)); }                       \
                tau1 = __shfl_sync(FULLMASK, topd, 31);                          \
            }                                                                    \
        }                                                                        \
    }

    // Block-cooperative tile scan over a contiguous sorted-point range.
    // Must be called with block-uniform (s, e).
    auto scan_pts = [&](int s, int e) {
        for (int t0 = s; t0 < e; t0 += TILE) {
            const int cnt = min(TILE, e - t0);
            __syncthreads();
            for (int i = tid; i < cnt; i += TPB)
                sp[i] = g_spts[b * NN + t0 + i];
            __syncthreads();
            if (cnt == TILE) {
                for (int j = 0; j < TILE; j += 64) KNN_CHUNK(j, TILE, false, t0)
            } else {
                for (int j = 0; j < cnt; j += 64) KNN_CHUNK(j, cnt, true, t0)
            }
        }
    };

    int a  = bin_of(xlo);
    int bh = bin_of(xhi);
    int lo = g_pstart[bsb + a];
    int hi = g_pstart[bsb + bh + 1];

    scan_pts(lo, hi);

    // ---- Phase 3: block-uniform exact expansion loop (safety net) ----
    for (;;) {
        const float t20 = tau0 + qq0;           // real squared 16th distances
        const float t21 = tau1 + qq1;
        const float l0 = t20 + 1e-5f + 4e-6f * fabsf(t20);
        const float l1 = t21 + 1e-5f + 4e-6f * fabsf(t21);
        const float xl = BINLO + a * BINW + 1e-4f;          // conservative edges
        const float xr = BINLO + (bh + 1) * BINW - 1e-4f;
        const float gl0 = qx0 - xl, gl1 = qx1 - xl;
        const float gr0 = xr - qx0, gr1 = xr - qx1;
        const bool needL = (a > 0) && (gl0 * gl0 < l0 || gl1 * gl1 < l1);
        const bool needR = (bh < NBIN - 1) && (gr0 * gr0 < l0 || gr1 * gr1 < l1);
        const int anyL = __syncthreads_or(needL ? 1 : 0);
        const int anyR = __syncthreads_or(needR ? 1 : 0);
        if (!(anyL | anyR)) break;
        if (anyL) {
            const int na  = max(a - STEPB, 0);
            const int nlo = g_pstart[bsb + na];
            scan_pts(nlo, lo);
            a = na; lo = nlo;
        }
        if (anyR) {
            const int nb  = min(bh + STEPB, NBIN - 1);
            const int nhi = g_pstart[bsb + nb + 1];
            scan_pts(hi, nhi);
            bh = nb; hi = nhi;
        }
    }
#undef KNN_CHUNK

    // --- fused gather/mean for both queries (original indices in topi) ---
    const float* ft = g_xt + (size_t)b * NN * CC;
    float a0 = 0.0f, a1 = 0.0f;   // q0: channels [lane], [lane+32]
    float c0 = 0.0f, c1 = 0.0f;   // q1
#pragma unroll
    for (int r = 0; r < KK; r++) {
        const int gA = __shfl_sync(FULLMASK, topi, r);
        const int gB = __shfl_sync(FULLMASK, topi, 16 + r);
        const float* fA = ft + (size_t)gA * CC;
        const float* fB = ft + (size_t)gB * CC;
        a0 += fA[lane];
        a1 += fA[lane + 32];
        c0 += fB[lane];
        c1 += fB[lane + 32];
    }

    out[((size_t)b * CC + lane) * MM + m0]        = a0 * (1.0f / KK);
    out[((size_t)b * CC + lane + 32) * MM + m0]   = a1 * (1.0f / KK);
    out[((size_t)b * CC + lane) * MM + m1]        = c0 * (1.0f / KK);
    out[((size_t)b * CC + lane + 32) * MM + m1]   = c1 * (1.0f / KK);
}

// ---------------------------------------------------------------------------
extern "C" void kernel_launch(void* const* d_in, const int* in_sizes, int n_in,
                              void* d_out, int out_size) {
    const float* p1 = (const float*)d_in[0];   // (B, N, 3)
    const float* x1 = (const float*)d_in[1];   // (B, C, N)
    const float* p2 = (const float*)d_in[2];   // (B, M, 3)
    float* out = (float*)d_out;                // (B, C, M)

    zero_kernel<<<8, 256>>>();
    count_kernel<<<160, 256>>>(p1, p2);
    scan_kernel<<<4, 1024>>>();
    scatter_kernel<<<160, 256>>>(p1, p2);

    dim3 tb(32, 8);
    dim3 tg(NN / 32, CC / 32, BB);
    transpose_kernel<<<tg, tb>>>(x1);

    knn_kernel<<<NQ / QPB, TPB>>>(p2, out);
}

// round 16
// speedup vs baseline: 1.5650x; 1.5650x over previous
#include <cuda_runtime.h>

// Problem constants (fixed shapes from reference)
#define BB    2
#define NN    16384
#define MM    4096
#define CC    64
#define KK    16
#define TILE  1024            // points per pipeline stage
#define NTILE (NN / TILE)     // 16 stages
#define WPB   8               // warps per block (each warp = 2 queries)
#define TPB   256
#define NQ    (BB * MM)       // 8192 queries
#define NP    (NQ / 2)        // 4096 query pairs

#define BIGF 1e30f
#define FULLMASK 0xffffffffu

// Scratch (__device__ globals; no allocs allowed)
__device__ float  g_xt[BB * NN * CC];   // transposed features (B,N,C), 8 MB
__device__ float4 g_pts[BB * NN];       // packed points (x,y,z,|p|^2)

// ---------------------------------------------------------------------------
// Kernel 0: pack p1 (B,N,3) -> float4 (x, y, z, |p|^2)
// ---------------------------------------------------------------------------
__global__ __launch_bounds__(256) void pack_kernel(const float* __restrict__ p1) {
    const int i = blockIdx.x * 256 + threadIdx.x;  // 0 .. BB*NN-1
    const float x = p1[i * 3 + 0];
    const float y = p1[i * 3 + 1];
    const float z = p1[i * 3 + 2];
    g_pts[i] = make_float4(x, y, z, fmaf(x, x, fmaf(y, y, z * z)));
}

// ---------------------------------------------------------------------------
// Kernel 1: transpose x1 (B,C,N) -> g_xt (B,N,C) so neighbor gathers coalesce.
// ---------------------------------------------------------------------------
__global__ __launch_bounds__(256) void transpose_kernel(const float* __restrict__ x1) {
    __shared__ float t[32][33];
    const int b  = blockIdx.z;
    const int n0 = blockIdx.x * 32;
    const int c0 = blockIdx.y * 32;
    const int tx = threadIdx.x;
    const int ty = threadIdx.y;

    const float* src = x1  + (size_t)b * CC * NN;
    float*       dst = g_xt + (size_t)b * NN * CC;

#pragma unroll
    for (int i = 0; i < 32; i += 8)
        t[ty + i][tx] = src[(size_t)(c0 + ty + i) * NN + (n0 + tx)];
    __syncthreads();
#pragma unroll
    for (int i = 0; i < 32; i += 8)
        dst[(size_t)(n0 + ty + i) * CC + (c0 + tx)] = t[tx][ty + i];
}

// ---------------------------------------------------------------------------
// Kernel 2: full-scan warp-distributed exact KNN(16), two queries per warp,
// fused gather/mean. R8 structure with:
//   - cp.async double-buffered tile staging (kills the LDG+STS staging loop)
//   - bitonic warp-sort init of both top-16 lists from the first 32 points
//   - single combined gate ballot per 64-point chunk
// Lanes 0..15 hold q0's sorted top-16; lanes 16..31 q1's. Deterministic:
// original point order, no atomics. d' = |p|^2 - 2 q.p (order-equivalent).
// ---------------------------------------------------------------------------
__global__ __launch_bounds__(TPB) void knn_kernel(const float* __restrict__ p2,
                                                  float* __restrict__ out) {
    __shared__ float4 sp[2][TILE];   // 2 x 16 KB

    const int tid  = threadIdx.x;
    const int warp = tid >> 5, lane = tid & 31;
    const int pairId = blockIdx.x * WPB + warp;   // 0..NP-1
    const int b    = pairId >> 11;                // / (MM/2)
    const int m0   = (pairId & 2047) * 2;

    const float* qp = p2 + ((size_t)b * MM + m0) * 3;
    const float n0x = -2.0f * qp[0], n0y = -2.0f * qp[1], n0z = -2.0f * qp[2];
    const float n1x = -2.0f * qp[3], n1y = -2.0f * qp[4], n1z = -2.0f * qp[5];

    const float4* gp = g_pts + (size_t)b * NN;

    // ---- issue first two tile loads (cp.async, 4 x 16B per thread) ----
#define ISSUE_TILE(BUF, T)                                                      \
    {                                                                           \
        const float4* _src = gp + (T) * TILE + tid;                             \
        unsigned _dst = (unsigned)__cvta_generic_to_shared(&sp[(BUF)][tid]);    \
        _Pragma("unroll")                                                       \
        for (int _k = 0; _k < TILE / TPB; _k++)                                 \
            asm volatile("cp.async.cg.shared.global [%0], [%1], 16;"            \
                         :: "r"(_dst + _k * TPB * 16), "l"(_src + _k * TPB));   \
        asm volatile("cp.async.commit_group;");                                 \
    }

    ISSUE_TILE(0, 0)
    ISSUE_TILE(1, 1)

    // ---- init: exact top-16 of points 0..31 via full warp bitonic sort ----
    float topd;                  // sorted lists: q0 lanes 0..15, q1 lanes 16..31
    int   topi;
    {
        const float4 Pi = gp[lane];            // direct LDG (L2), overlaps cp.async
        float s0 = fmaf(n0x, Pi.x, fmaf(n0y, Pi.y, fmaf(n0z, Pi.z, Pi.w)));
        float s1 = fmaf(n1x, Pi.x, fmaf(n1y, Pi.y, fmaf(n1z, Pi.z, Pi.w)));
        int   i0 = lane, i1 = lane;
#pragma unroll
        for (int k = 2; k <= 32; k <<= 1) {
#pragma unroll
            for (int j = k >> 1; j; j >>= 1) {
                {
                    const float od = __shfl_xor_sync(FULLMASK, s0, j);
                    const int   oi = __shfl_xor_sync(FULLMASK, i0, j);
                    const bool keepMin = (((lane & k) == 0) == ((lane & j) == 0));
                    const bool sw = keepMin ? (od < s0) : (od > s0);
                    if (sw) { s0 = od; i0 = oi; }
                }
                {
                    const float od = __shfl_xor_sync(FULLMASK, s1, j);
                    const int   oi = __shfl_xor_sync(FULLMASK, i1, j);
                    const bool keepMin = (((lane & k) == 0) == ((lane & j) == 0));
                    const bool sw = keepMin ? (od < s1) : (od > s1);
                    if (sw) { s1 = od; i1 = oi; }
                }
            }
        }
        const float s1s = __shfl_sync(FULLMASK, s1, (lane + 16) & 31);
        const int   i1s = __shfl_sync(FULLMASK, i1, (lane + 16) & 31);
        topd = (lane < 16) ? s0 : s1s;
        topi = (lane < 16) ? i0 : i1s;
    }
    float tau0 = __shfl_sync(FULLMASK, topd, 15);
    float tau1 = __shfl_sync(FULLMASK, topd, 31);

    auto ins0 = [&](float dc, int ic) {
        const int rank = __popc(__ballot_sync(FULLMASK, topd < dc) & 0xFFFFu);
        const float pd = __shfl_up_sync(FULLMASK, topd, 1);
        const int   pi = __shfl_up_sync(FULLMASK, topi, 1);
        if (lane < 16) {
            if (lane == rank)     { topd = dc; topi = ic; }
            else if (lane > rank) { topd = pd; topi = pi; }
        }
    };
    auto ins1 = [&](float dc, int ic) {
        const int rank = 16 + __popc(__ballot_sync(FULLMASK, topd < dc) >> 16);
        const float pd = __shfl_up_sync(FULLMASK, topd, 1);
        const int   pi = __shfl_up_sync(FULLMASK, topi, 1);
        if (lane >= 16) {
            if (lane == rank)     { topd = dc; topi = ic; }
            else if (lane > rank) { topd = pd; topi = pi; }
        }
    };

#define KNN_CHUNK(BUF, J, BASE)                                                  \
    {                                                                            \
        const float4 Pa = sp[(BUF)][(J) + lane];                                 \
        const float4 Pb = sp[(BUF)][(J) + 32 + lane];                            \
        const float d0a = fmaf(n0x, Pa.x, fmaf(n0y, Pa.y, fmaf(n0z, Pa.z, Pa.w)));\
        const float d0b = fmaf(n0x, Pb.x, fmaf(n0y, Pb.y, fmaf(n0z, Pb.z, Pb.w)));\
        const float d1a = fmaf(n1x, Pa.x, fmaf(n1y, Pa.y, fmaf(n1z, Pa.z, Pa.w)));\
        const float d1b = fmaf(n1x, Pb.x, fmaf(n1y, Pb.y, fmaf(n1z, Pb.z, Pb.w)));\
        const unsigned gate = __ballot_sync(FULLMASK,                            \
            (fminf(d0a, d0b) < tau0) || (fminf(d1a, d1b) < tau1));               \
        if (gate) {                                                              \
            const int ia = (BASE) + (J) + lane;                                  \
            unsigned ba = __ballot_sync(FULLMASK, d0a < tau0);                   \
            unsigned bc = __ballot_sync(FULLMASK, d0b < tau0);                   \
            if (ba | bc) {                                                       \
                while (ba) { const int s2 = __ffs(ba) - 1; ba &= ba - 1;         \
                    ins0(__shfl_sync(FULLMASK, d0a, s2),                         \
                         __shfl_sync(FULLMASK, ia, s2)); }                       \
                while (bc) { const int s2 = __ffs(bc) - 1; bc &= bc - 1;         \
                    ins0(__shfl_sync(FULLMASK, d0b, s2),                         \
                         __shfl_sync(FULLMASK, ia, s2) + 32); }                  \
                tau0 = __shfl_sync(FULLMASK, topd, 15);                          \
            }                                                                    \
            unsigned be = __ballot_sync(FULLMASK, d1a < tau1);                   \
            unsigned bf = __ballot_sync(FULLMASK, d1b < tau1);                   \
            if (be | bf) {                                                       \
                while (be) { const int s2 = __ffs(be) - 1; be &= be - 1;         \
                    ins1(__shfl_sync(FULLMASK, d1a, s2),                         \
                         __shfl_sync(FULLMASK, ia, s2)); }                       \
                while (bf) { const int s2 = __ffs(bf) - 1; bf &= bf - 1;         \
                    ins1(__shfl_sync(FULLMASK, d1b, s2),                         \
                         __shfl_sync(FULLMASK, ia, s2) + 32); }                  \
                tau1 = __shfl_sync(FULLMASK, topd, 31);                          \
            }                                                                    \
        }                                                                        \
    }

    // ---- main double-buffered pipeline over 16 tiles ----
    for (int t = 0; t < NTILE; t++) {
        if (t < NTILE - 1) asm volatile("cp.async.wait_group 1;");
        else               asm volatile("cp.async.wait_group 0;");
        __syncthreads();

        const int buf  = t & 1;
        const int base = t * TILE;
        if (t == 0) {
            // points 0..31 already consumed by the sort init; do 32..63, then 64..
            {
                const float4 Pa = sp[0][32 + lane];
                const float d0a = fmaf(n0x, Pa.x, fmaf(n0y, Pa.y, fmaf(n0z, Pa.z, Pa.w)));
                const float d1a = fmaf(n1x, Pa.x, fmaf(n1y, Pa.y, fmaf(n1z, Pa.z, Pa.w)));
                const unsigned gate = __ballot_sync(FULLMASK, (d0a < tau0) || (d1a < tau1));
                if (gate) {
                    const int ia = 32 + lane;
                    unsigned ba = __ballot_sync(FULLMASK, d0a < tau0);
                    if (ba) {
                        while (ba) { const int s2 = __ffs(ba) - 1; ba &= ba - 1;
                            ins0(__shfl_sync(FULLMASK, d0a, s2),
                                 __shfl_sync(FULLMASK, ia, s2)); }
                        tau0 = __shfl_sync(FULLMASK, topd, 15);
                    }
                    unsigned be = __ballot_sync(FULLMASK, d1a < tau1);
                    if (be) {
                        while (be) { const int s2 = __ffs(be) - 1; be &= be - 1;
                            ins1(__shfl_sync(FULLMASK, d1a, s2),
                                 __shfl_sync(FULLMASK, ia, s2)); }
                        tau1 = __shfl_sync(FULLMASK, topd, 31);
                    }
                }
            }
            for (int j = 64; j < TILE; j += 64) KNN_CHUNK(0, j, 0)
        } else {
#pragma unroll 4
            for (int j = 0; j < TILE; j += 64) KNN_CHUNK(buf, j, base)
        }
        __syncthreads();
        if (t + 2 < NTILE) ISSUE_TILE(buf, t + 2)
    }
#undef KNN_CHUNK
#undef ISSUE_TILE

    // ---- fused gather/mean for both queries (lists sorted; order irrelevant) ----
    const float* ft = g_xt + (size_t)b * NN * CC;
    float a0 = 0.0f, a1 = 0.0f;   // q0: channels [lane], [lane+32]
    float c0 = 0.0f, c1 = 0.0f;   // q1
#pragma unroll
    for (int r = 0; r < KK; r++) {
        const int gA = __shfl_sync(FULLMASK, topi, r);
        const int gB = __shfl_sync(FULLMASK, topi, 16 + r);
        const float* fA = ft + (size_t)gA * CC;
        const float* fB = ft + (size_t)gB * CC;
        a0 += fA[lane];
        a1 += fA[lane + 32];
        c0 += fB[lane];
        c1 += fB[lane + 32];
    }

    const size_t obase = ((size_t)b * CC + lane) * MM + m0;
    out[obase]                       = a0 * (1.0f / KK);
    out[obase + (size_t)32 * MM]     = a1 * (1.0f / KK);
    out[obase + 1]                   = c0 * (1.0f / KK);
    out[obase + (size_t)32 * MM + 1] = c1 * (1.0f / KK);
}

// ---------------------------------------------------------------------------
extern "C" void kernel_launch(void* const* d_in, const int* in_sizes, int n_in,
                              void* d_out, int out_size) {
    const float* p1 = (const float*)d_in[0];   // (B, N, 3)
    const float* x1 = (const float*)d_in[1];   // (B, C, N)
    const float* p2 = (const float*)d_in[2];   // (B, M, 3)
    float* out = (float*)d_out;                // (B, C, M)

    pack_kernel<<<(BB * NN) / 256, 256>>>(p1);

    dim3 tb(32, 8);
    dim3 tg(NN / 32, CC / 32, BB);
    transpose_kernel<<<tg, tb>>>(x1);

    knn_kernel<<<NP / WPB, TPB>>>(p2, out);
}